// round 16
// baseline (speedup 1.0000x reference)
#include <cuda_runtime.h>
#include <cuda_bf16.h>

// CRF batched Viterbi+forward, LPT-scheduled dynamic queue.
// Ordering via parallel direct-rank (no single-block sort bottleneck).

#define BB 2048
#define TT 512
#define KK 32
#define NEG_INF (-3.4e38f)
#define NCTA (148 * 13)
#define RNK_THREADS 128
#define RNK_BLOCKS (BB / RNK_THREADS)

__device__ unsigned g_qhead;
__device__ unsigned g_sched[BB];

// Exact LPT order: rank(i) = #{j: len_j > len_i} + #{j<i: len_j == len_i}.
// Strict total order on (-len, idx) -> ranks are a permutation; no atomics.
__global__ void crf_rank_kernel(const int* __restrict__ lens)
{
    __shared__ int L[BB];
    const int tid = threadIdx.x;
    for (int i = tid; i < BB; i += RNK_THREADS)
        L[i] = lens[i];
    __syncthreads();

    const int i  = blockIdx.x * RNK_THREADS + tid;
    const int li = L[i];
    int rank = 0;
#pragma unroll 8
    for (int j = 0; j < BB; j++) {
        int lj = L[j];
        rank += (int)((lj > li) | ((lj == li) & (j < i)));
    }
    g_sched[rank] = (unsigned)i;
    if (i == 0) g_qhead = 0u;
}

// One warp per CTA; queue dispenses items longest-first (LPT), so all warps
// drain within ~one short item of each other. Step math identical to R8/R15.
__global__ __launch_bounds__(32) void crf_main_kernel(
    const float* __restrict__ pot,     // [B,T,K]
    const float* __restrict__ trans,   // [K,K]
    const int*   __restrict__ lens,    // [B]
    const int*   __restrict__ tagidx,  // [B,T]
    float*       __restrict__ out)     // [B*T] tags, [B] best, [B] loglik
{
    const int lane = threadIdx.x;

    __shared__ unsigned char bp_sm[TT * KK];
    __shared__ __align__(16) float2 xbuf[2][KK];   // (aV, pexp) interleaved
    __shared__ __align__(16) unsigned char tags_sm[TT];

    float tc[KK], ec[KK];
#pragma unroll
    for (int j = 0; j < KK; j++) {
        float v = trans[j * KK + lane];
        tc[j] = v;
        ec[j] = __expf(v);
    }

    for (;;) {
        unsigned r = 0;
        if (lane == 0) r = atomicAdd(&g_qhead, 1u);
        r = __shfl_sync(0xffffffffu, r, 0);
        if (r >= BB) break;
        const int b = (int)g_sched[r];

        const int len = lens[b];
        const float* pb = pot + (size_t)b * (TT * KK);

        float aV = pb[lane];
        float aF = aV;
        float mcur = __shfl_sync(0xffffffffu, aF, 0);

        // prefetch ring, depth 4 (rows 1..4 in-bounds, TT=512)
        float q0 = pb[1 * KK + lane];
        float q1 = pb[2 * KK + lane];
        float q2 = pb[3 * KK + lane];
        float q3 = pb[4 * KK + lane];

        auto step = [&](float pt, int t, int buf) {
            float pexp = __expf(aF - mcur);
            xbuf[buf][lane] = make_float2(aV, pexp);
            __syncwarp();
            const float4* x4 = (const float4*)xbuf[buf];   // 2 j's per float4

            float m0 = NEG_INF, m1 = NEG_INF, m2 = NEG_INF, m3 = NEG_INF;
            int   i0 = 0, i1 = 0, i2 = 0, i3 = 0;
            float s0 = 0.f, s1 = 0.f, s2 = 0.f, s3 = 0.f;
#pragma unroll
            for (int q = 0; q < 8; q++) {
                float4 xa = x4[2 * q];       // j = 4q, 4q+1 : (aV,p,aV,p)
                float4 xb = x4[2 * q + 1];   // j = 4q+2, 4q+3
                float v0 = xa.x + tc[4*q+0];
                float v1 = xa.z + tc[4*q+1];
                float v2 = xb.x + tc[4*q+2];
                float v3 = xb.z + tc[4*q+3];
                bool g0 = v0 > m0; i0 = g0 ? (4*q+0) : i0; m0 = g0 ? v0 : m0;
                bool g1 = v1 > m1; i1 = g1 ? (4*q+1) : i1; m1 = g1 ? v1 : m1;
                bool g2 = v2 > m2; i2 = g2 ? (4*q+2) : i2; m2 = g2 ? v2 : m2;
                bool g3 = v3 > m3; i3 = g3 ? (4*q+3) : i3; m3 = g3 ? v3 : m3;
                s0 += xa.y * ec[4*q+0];
                s1 += xa.w * ec[4*q+1];
                s2 += xb.y * ec[4*q+2];
                s3 += xb.w * ec[4*q+3];
            }
            float best = m0; int arg = i0;
            bool c1 = (m1 > best) || ((m1 == best) && (i1 < arg));
            arg  = c1 ? i1 : arg;  best = c1 ? m1 : best;
            bool c2 = (m2 > best) || ((m2 == best) && (i2 < arg));
            arg  = c2 ? i2 : arg;  best = c2 ? m2 : best;
            bool c3 = (m3 > best) || ((m3 == best) && (i3 < arg));
            arg  = c3 ? i3 : arg;  best = c3 ? m3 : best;
            float ssum = (s0 + s1) + (s2 + s3);

            bp_sm[t * KK + lane] = (unsigned char)arg;
            aV = pt + best;
            aF = pt + (mcur + __logf(ssum));
            mcur = __shfl_sync(0xffffffffu, aF, 0);   // uniform offset = new aF lane 0
        };

        int t = 1;
        for (; t + 3 < len; t += 4) {
            int c4 = min(t + 4, TT - 1), c5 = min(t + 5, TT - 1);
            int c6 = min(t + 6, TT - 1), c7 = min(t + 7, TT - 1);
            float n0 = pb[c4 * KK + lane];
            float n1 = pb[c5 * KK + lane];
            float n2 = pb[c6 * KK + lane];
            float n3 = pb[c7 * KK + lane];
            step(q0, t + 0, 1);
            step(q1, t + 1, 0);
            step(q2, t + 2, 1);
            step(q3, t + 3, 0);
            q0 = n0; q1 = n1; q2 = n2; q3 = n3;
        }
        if (t < len) { step(q0, t, 1); t++; }
        if (t < len) { step(q1, t, 0); t++; }
        if (t < len) { step(q2, t, 1); }
        __syncwarp();

        // ---- Viterbi terminal: best_score + last_tag (first max index) ----
        float mv = aV;
#pragma unroll
        for (int s = 16; s; s >>= 1)
            mv = fmaxf(mv, __shfl_xor_sync(0xffffffffu, mv, s));
        unsigned msk = __ballot_sync(0xffffffffu, aV == mv);
        int last_tag = __ffs(msk) - 1;

        // ---- exact final logsumexp ----
        float mf = aF;
#pragma unroll
        for (int s = 16; s; s >>= 1)
            mf = fmaxf(mf, __shfl_xor_sync(0xffffffffu, mf, s));
        float ex = __expf(aF - mf);
#pragma unroll
        for (int s = 16; s; s >>= 1)
            ex += __shfl_xor_sync(0xffffffffu, ex, s);
        float log_norm = mf + __logf(ex);

        // ---- tags: fill with last_tag, then backtrace over smem ----
        unsigned rep = (unsigned)last_tag * 0x01010101u;
#pragma unroll
        for (int w = 0; w < 4; w++)
            ((unsigned*)tags_sm)[w * 32 + lane] = rep;
        __syncwarp();

        if (lane == 0) {
            int tg = last_tag;
            for (int tt = len - 1; tt >= 1; tt--) {
                tg = bp_sm[tt * KK + tg];
                tags_sm[tt - 1] = (unsigned char)tg;
            }
        }
        __syncwarp();

        float* otags = out + (size_t)b * TT;
#pragma unroll
        for (int c = 0; c < 4; c++) {
            uchar4 u = ((const uchar4*)tags_sm)[c * 32 + lane];
            ((float4*)otags)[c * 32 + lane] =
                make_float4((float)u.x, (float)u.y, (float)u.z, (float)u.w);
        }

        // ---- gold sequence score (branch-free) ----
        const int* ti = tagidx + (size_t)b * TT;
        float acc = 0.f;
#pragma unroll 4
        for (int tt = lane; tt < TT; tt += 32) {
            int tg = ti[tt];
            float u  = pb[tt * KK + tg];
            int   tn = ti[min(tt + 1, TT - 1)];
            float w  = trans[tg * KK + tn];
            acc += (tt < len)     ? u : 0.f;
            acc += (tt < len - 1) ? w : 0.f;
        }
#pragma unroll
        for (int s = 16; s; s >>= 1)
            acc += __shfl_xor_sync(0xffffffffu, acc, s);

        if (lane == 0) {
            out[(size_t)BB * TT + b]      = mv;               // best_score
            out[(size_t)BB * TT + BB + b] = acc - log_norm;   // log_likelihood
        }
    }
}

extern "C" void kernel_launch(void* const* d_in, const int* in_sizes, int n_in,
                              void* d_out, int out_size) {
    const float* pot = nullptr;
    const float* trn = nullptr;
    const int*   len = nullptr;
    const int*   tgi = nullptr;
    for (int i = 0; i < n_in; i++) {
        switch (in_sizes[i]) {
            case 33554432: pot = (const float*)d_in[i]; break;
            case 1024:     trn = (const float*)d_in[i]; break;
            case 2048:     len = (const int*)d_in[i];   break;
            case 1048576:  tgi = (const int*)d_in[i];   break;
            default: break;
        }
    }
    float* out = (float*)d_out;
    crf_rank_kernel<<<RNK_BLOCKS, RNK_THREADS>>>(len);
    crf_main_kernel<<<NCTA, 32>>>(pot, trn, len, tgi, out);
    (void)out_size;
}